// round 1
// baseline (speedup 1.0000x reference)
#include <cuda_runtime.h>

#define D 128
#define T_TYPES 4
#define MAX_N 50000
#define MAX_E 500000
#define EPS 1e-5f

// ---------------- scratch (static __device__ globals; no allocation) ----------------
__device__ float g_Y[(size_t)T_TYPES * MAX_N * D];   // Y_t = x @ W_types[t]
__device__ float g_acc1[(size_t)MAX_N * D];          // scattered type-messages (final space)
__device__ float g_acc2[(size_t)MAX_N * D];          // scattered H = relu(EF@W1+b1) (pre-W2 space)
__device__ int   g_deg[T_TYPES * MAX_N];             // per (type,row) in-degree

__device__ __forceinline__ void red_add_v4(float* addr, float4 v) {
    asm volatile("red.global.add.v4.f32 [%0], {%1, %2, %3, %4};"
                 :: "l"(addr), "f"(v.x), "f"(v.y), "f"(v.z), "f"(v.w) : "memory");
}

// ---------------- zero scratch ----------------
__global__ void zero_kernel(int n) {
    size_t idx = (size_t)blockIdx.x * blockDim.x + threadIdx.x;
    size_t stride = (size_t)gridDim.x * blockDim.x;
    size_t n4 = (size_t)n * D / 4;
    float4 z = make_float4(0.f, 0.f, 0.f, 0.f);
    for (size_t i = idx; i < n4; i += stride) {
        reinterpret_cast<float4*>(g_acc1)[i] = z;
        reinterpret_cast<float4*>(g_acc2)[i] = z;
    }
    size_t nd = (size_t)T_TYPES * n;
    for (size_t i = idx; i < nd; i += stride) g_deg[i] = 0;
}

// ---------------- K1: Y[t] = x @ W_types[t]  (M=n, K=128, N=128) ----------------
__global__ void __launch_bounds__(256) y_gemm(const float* __restrict__ x,
                                             const float* __restrict__ Wt,
                                             int n) {
    int t = blockIdx.y;
    int m0 = blockIdx.x * 128;
    const float* B = Wt + (size_t)t * D * D;
    float* C = g_Y + (size_t)t * n * D;

    __shared__ float As[8][128];
    __shared__ float Bs[8][128];

    int tid = threadIdx.x;
    int tx = tid & 15, ty = tid >> 4;
    int lm = tid >> 1;          // A loader: row 0..127
    int lk = (tid & 1) * 4;     // A loader: k offset 0/4
    int bk = tid >> 5;          // B loader: k row 0..7
    int bn = (tid & 31) * 4;    // B loader: col

    float c[8][8];
    #pragma unroll
    for (int i = 0; i < 8; i++)
        #pragma unroll
        for (int j = 0; j < 8; j++) c[i][j] = 0.f;

    for (int kt = 0; kt < D; kt += 8) {
        int gm = m0 + lm;
        float4 a4 = make_float4(0.f, 0.f, 0.f, 0.f);
        if (gm < n) a4 = *reinterpret_cast<const float4*>(x + (size_t)gm * D + kt + lk);
        As[lk + 0][lm] = a4.x; As[lk + 1][lm] = a4.y;
        As[lk + 2][lm] = a4.z; As[lk + 3][lm] = a4.w;
        float4 b4 = *reinterpret_cast<const float4*>(B + (size_t)(kt + bk) * D + bn);
        *reinterpret_cast<float4*>(&Bs[bk][bn]) = b4;
        __syncthreads();
        #pragma unroll
        for (int k = 0; k < 8; k++) {
            float a[8], b[8];
            #pragma unroll
            for (int i = 0; i < 8; i++) a[i] = As[k][ty * 8 + i];
            #pragma unroll
            for (int j = 0; j < 8; j++) b[j] = Bs[k][tx * 8 + j];
            #pragma unroll
            for (int i = 0; i < 8; i++)
                #pragma unroll
                for (int j = 0; j < 8; j++) c[i][j] += a[i] * b[j];
        }
        __syncthreads();
    }
    #pragma unroll
    for (int i = 0; i < 8; i++) {
        int gm = m0 + ty * 8 + i;
        if (gm < n) {
            float* cp = C + (size_t)gm * D + tx * 8;
            *reinterpret_cast<float4*>(cp)     = make_float4(c[i][0], c[i][1], c[i][2], c[i][3]);
            *reinterpret_cast<float4*>(cp + 4) = make_float4(c[i][4], c[i][5], c[i][6], c[i][7]);
        }
    }
}

// ---------------- K2: per-edge-tile H GEMM + scatter ----------------
// H = relu(EF @ W_e1 + b_e1) -> red into g_acc2[row]
// Y[type][col]               -> red into g_acc1[row]
// deg counts
__global__ void __launch_bounds__(256) edge_kernel(const float* __restrict__ ef,
                                                   const float* __restrict__ W1,
                                                   const float* __restrict__ b1,
                                                   const int* __restrict__ erow,
                                                   const int* __restrict__ ecol,
                                                   const int* __restrict__ etype,
                                                   int E, int n) {
    int m0 = blockIdx.x * 128;

    __shared__ float As[8][128];
    __shared__ float Bs[8][128];
    __shared__ float sb1[128];
    __shared__ int s_row[128], s_col[128], s_type[128];

    int tid = threadIdx.x;
    int tx = tid & 15, ty = tid >> 4;
    int lm = tid >> 1;
    int lk = (tid & 1) * 4;
    int bk = tid >> 5;
    int bn = (tid & 31) * 4;

    if (tid < 128) {
        sb1[tid] = b1[tid];
        int e = m0 + tid;
        if (e < E) {
            int r = erow[e];
            int t = etype[e];
            s_row[tid] = r;
            s_col[tid] = ecol[e];
            s_type[tid] = t;
            atomicAdd(&g_deg[(size_t)t * n + r], 1);
        }
    }

    float c[8][8];
    #pragma unroll
    for (int i = 0; i < 8; i++)
        #pragma unroll
        for (int j = 0; j < 8; j++) c[i][j] = 0.f;

    for (int kt = 0; kt < D; kt += 8) {
        int gm = m0 + lm;
        float4 a4 = make_float4(0.f, 0.f, 0.f, 0.f);
        if (gm < E) a4 = *reinterpret_cast<const float4*>(ef + (size_t)gm * D + kt + lk);
        As[lk + 0][lm] = a4.x; As[lk + 1][lm] = a4.y;
        As[lk + 2][lm] = a4.z; As[lk + 3][lm] = a4.w;
        float4 b4 = *reinterpret_cast<const float4*>(W1 + (size_t)(kt + bk) * D + bn);
        *reinterpret_cast<float4*>(&Bs[bk][bn]) = b4;
        __syncthreads();
        #pragma unroll
        for (int k = 0; k < 8; k++) {
            float a[8], b[8];
            #pragma unroll
            for (int i = 0; i < 8; i++) a[i] = As[k][ty * 8 + i];
            #pragma unroll
            for (int j = 0; j < 8; j++) b[j] = Bs[k][tx * 8 + j];
            #pragma unroll
            for (int i = 0; i < 8; i++)
                #pragma unroll
                for (int j = 0; j < 8; j++) c[i][j] += a[i] * b[j];
        }
        __syncthreads();
    }

    // epilogue: relu + bias, scatter H and Y
    #pragma unroll
    for (int i = 0; i < 8; i++) {
        int le = ty * 8 + i;
        int e = m0 + le;
        if (e >= E) continue;
        int r = s_row[le];
        int cn = s_col[le];
        int t = s_type[le];
        float h[8];
        #pragma unroll
        for (int j = 0; j < 8; j++) h[j] = fmaxf(c[i][j] + sb1[tx * 8 + j], 0.f);
        float* a2 = g_acc2 + (size_t)r * D + tx * 8;
        red_add_v4(a2,     make_float4(h[0], h[1], h[2], h[3]));
        red_add_v4(a2 + 4, make_float4(h[4], h[5], h[6], h[7]));
        const float4* yp = reinterpret_cast<const float4*>(
            g_Y + ((size_t)t * n + cn) * D + tx * 8);
        float4 y0 = yp[0], y1 = yp[1];
        float* a1 = g_acc1 + (size_t)r * D + tx * 8;
        red_add_v4(a1,     y0);
        red_add_v4(a1 + 4, y1);
    }
}

// ---------------- K3: out = LN(acc1 + acc2@W_e2 + x@W_self + biases) -> relu ----------------
__global__ void __launch_bounds__(256) final_kernel(const float* __restrict__ x,
                                                    const float* __restrict__ We2,
                                                    const float* __restrict__ Wself,
                                                    const float* __restrict__ bself,
                                                    const float* __restrict__ btypes,
                                                    const float* __restrict__ be2,
                                                    const float* __restrict__ lng,
                                                    const float* __restrict__ lnb,
                                                    float* __restrict__ out,
                                                    int n) {
    int m0 = blockIdx.x * 128;

    __shared__ float As[8][128];
    __shared__ float Bs[8][128];
    __shared__ float s_bself[128], s_be2[128], s_g[128], s_lb[128];
    __shared__ float s_bt[T_TYPES][128];

    int tid = threadIdx.x;
    int tx = tid & 15, ty = tid >> 4;
    int lm = tid >> 1;
    int lk = (tid & 1) * 4;
    int bk = tid >> 5;
    int bn = (tid & 31) * 4;

    if (tid < 128) {
        s_bself[tid] = bself[tid];
        s_be2[tid] = be2[tid];
        s_g[tid] = lng[tid];
        s_lb[tid] = lnb[tid];
        #pragma unroll
        for (int t = 0; t < T_TYPES; t++) s_bt[t][tid] = btypes[t * D + tid];
    }

    float c[8][8];
    #pragma unroll
    for (int i = 0; i < 8; i++)
        #pragma unroll
        for (int j = 0; j < 8; j++) c[i][j] = 0.f;

    // K = 256: [0,128) -> acc2 @ W_e2 ; [128,256) -> x @ W_self
    for (int kt = 0; kt < 2 * D; kt += 8) {
        int gm = m0 + lm;
        float4 a4 = make_float4(0.f, 0.f, 0.f, 0.f);
        if (gm < n) {
            const float* asrc = (kt < D) ? (g_acc2 + (size_t)gm * D + kt + lk)
                                         : (x + (size_t)gm * D + (kt - D) + lk);
            a4 = *reinterpret_cast<const float4*>(asrc);
        }
        As[lk + 0][lm] = a4.x; As[lk + 1][lm] = a4.y;
        As[lk + 2][lm] = a4.z; As[lk + 3][lm] = a4.w;
        const float* bsrc = (kt < D) ? (We2 + (size_t)(kt + bk) * D + bn)
                                     : (Wself + (size_t)(kt - D + bk) * D + bn);
        *reinterpret_cast<float4*>(&Bs[bk][bn]) = *reinterpret_cast<const float4*>(bsrc);
        __syncthreads();
        #pragma unroll
        for (int k = 0; k < 8; k++) {
            float a[8], b[8];
            #pragma unroll
            for (int i = 0; i < 8; i++) a[i] = As[k][ty * 8 + i];
            #pragma unroll
            for (int j = 0; j < 8; j++) b[j] = Bs[k][tx * 8 + j];
            #pragma unroll
            for (int i = 0; i < 8; i++)
                #pragma unroll
                for (int j = 0; j < 8; j++) c[i][j] += a[i] * b[j];
        }
        __syncthreads();
    }

    // epilogue: bias + LN + relu. Keep all lanes active for shuffles (clamp, guard stores).
    #pragma unroll
    for (int i = 0; i < 8; i++) {
        int gm = m0 + ty * 8 + i;
        int gmc = (gm < n) ? gm : (n - 1);
        int d0 = g_deg[0 * (size_t)n + gmc];
        int d1 = g_deg[1 * (size_t)n + gmc];
        int d2 = g_deg[2 * (size_t)n + gmc];
        int d3 = g_deg[3 * (size_t)n + gmc];
        float degs = (float)(d0 + d1 + d2 + d3);
        const float4* a1p = reinterpret_cast<const float4*>(g_acc1 + (size_t)gmc * D + tx * 8);
        float4 a10 = a1p[0], a11 = a1p[1];
        float av[8] = {a10.x, a10.y, a10.z, a10.w, a11.x, a11.y, a11.z, a11.w};
        float v[8];
        #pragma unroll
        for (int j = 0; j < 8; j++) {
            int col = tx * 8 + j;
            v[j] = c[i][j] + av[j] + s_bself[col]
                 + (float)d0 * s_bt[0][col] + (float)d1 * s_bt[1][col]
                 + (float)d2 * s_bt[2][col] + (float)d3 * s_bt[3][col]
                 + degs * s_be2[col];
        }
        float s = 0.f, sq = 0.f;
        #pragma unroll
        for (int j = 0; j < 8; j++) { s += v[j]; sq += v[j] * v[j]; }
        #pragma unroll
        for (int off = 8; off >= 1; off >>= 1) {
            s  += __shfl_xor_sync(0xffffffffu, s,  off);
            sq += __shfl_xor_sync(0xffffffffu, sq, off);
        }
        float mu = s * (1.f / 128.f);
        float var = sq * (1.f / 128.f) - mu * mu;
        float inv = rsqrtf(fmaxf(var, 0.f) + EPS);
        if (gm < n) {
            float o[8];
            #pragma unroll
            for (int j = 0; j < 8; j++) {
                int col = tx * 8 + j;
                o[j] = fmaxf((v[j] - mu) * inv * s_g[col] + s_lb[col], 0.f);
            }
            float* op = out + (size_t)gm * D + tx * 8;
            *reinterpret_cast<float4*>(op)     = make_float4(o[0], o[1], o[2], o[3]);
            *reinterpret_cast<float4*>(op + 4) = make_float4(o[4], o[5], o[6], o[7]);
        }
    }
}

// ---------------- launch ----------------
extern "C" void kernel_launch(void* const* d_in, const int* in_sizes, int n_in,
                              void* d_out, int out_size) {
    const float* x    = (const float*)d_in[0];
    const int*   ei   = (const int*)d_in[1];
    const int*   etyp = (const int*)d_in[2];
    const float* ef   = (const float*)d_in[3];
    const float* Wt   = (const float*)d_in[4];
    const float* bt   = (const float*)d_in[5];
    const float* Ws   = (const float*)d_in[6];
    const float* bs   = (const float*)d_in[7];
    const float* W1   = (const float*)d_in[8];
    const float* b1   = (const float*)d_in[9];
    const float* W2   = (const float*)d_in[10];
    const float* b2   = (const float*)d_in[11];
    const float* lg   = (const float*)d_in[12];
    const float* lb   = (const float*)d_in[13];
    float* out = (float*)d_out;

    int E = in_sizes[2];
    int n = in_sizes[0] / D;
    const int* erow = ei;       // edge_index[0] = destination (segment ids)
    const int* ecol = ei + E;   // edge_index[1] = source (gather ids)

    zero_kernel<<<1024, 256>>>(n);
    dim3 gy((n + 127) / 128, T_TYPES);
    y_gemm<<<gy, 256>>>(x, Wt, n);
    edge_kernel<<<(E + 127) / 128, 256>>>(ef, W1, b1, erow, ecol, etyp, E, n);
    final_kernel<<<(n + 127) / 128, 256>>>(x, W2, Ws, bs, bt, b2, lg, lb, out, n);
}

// round 2
// speedup vs baseline: 1.0610x; 1.0610x over previous
#include <cuda_runtime.h>

#define D 128
#define T_TYPES 4
#define MAX_N 50000
#define MAX_E 500000
#define EPS 1e-5f
#define KTILE 16

typedef unsigned long long u64;

// ---------------- scratch (static __device__ globals; no allocation) ----------------
__device__ float g_Y[(size_t)T_TYPES * MAX_N * D];   // Y_t = x @ W_types[t]
__device__ float g_acc1[(size_t)MAX_N * D];          // scattered type-messages (final space)
__device__ float g_acc2[(size_t)MAX_N * D];          // scattered H = relu(EF@W1+b1) (pre-W2 space)
__device__ int   g_deg[T_TYPES * MAX_N];             // per (type,row) in-degree

__device__ __forceinline__ void red_add_v4(float* addr, float4 v) {
    asm volatile("red.global.add.v4.f32 [%0], {%1, %2, %3, %4};"
                 :: "l"(addr), "f"(v.x), "f"(v.y), "f"(v.z), "f"(v.w) : "memory");
}
__device__ __forceinline__ u64 pack2(float lo, float hi) {
    u64 r; asm("mov.b64 %0, {%1, %2};" : "=l"(r) : "f"(lo), "f"(hi)); return r;
}
__device__ __forceinline__ void ffma2(u64& c, u64 a, u64 b) {
    asm("fma.rn.f32x2 %0, %1, %2, %0;" : "+l"(c) : "l"(a), "l"(b));
}
__device__ __forceinline__ float2 unpack2(u64 v) {
    float2 f; asm("mov.b64 {%0, %1}, %2;" : "=f"(f.x), "=f"(f.y) : "l"(v)); return f;
}

// ---------------- zero scratch ----------------
__global__ void zero_kernel(int n) {
    size_t idx = (size_t)blockIdx.x * blockDim.x + threadIdx.x;
    size_t stride = (size_t)gridDim.x * blockDim.x;
    size_t n4 = (size_t)n * D / 4;
    float4 z = make_float4(0.f, 0.f, 0.f, 0.f);
    for (size_t i = idx; i < n4; i += stride) {
        reinterpret_cast<float4*>(g_acc1)[i] = z;
        reinterpret_cast<float4*>(g_acc2)[i] = z;
    }
    size_t nd = (size_t)T_TYPES * n;
    for (size_t i = idx; i < nd; i += stride) g_deg[i] = 0;
}

// Shared GEMM-tile compute: accumulates cp[8][4] (f32x2 pairs) over one KTILE.
// As layout [k][m], Bs layout [k][n].
#define MMA_TILE_STEP(As, Bs, cp, tx, ty)                                   \
    _Pragma("unroll")                                                       \
    for (int k = 0; k < KTILE; k++) {                                       \
        float a_[8]; u64 bp_[4];                                            \
        const u64* brow_ = reinterpret_cast<const u64*>(&Bs[k][(tx) * 8]);  \
        bp_[0] = brow_[0]; bp_[1] = brow_[1];                               \
        bp_[2] = brow_[2]; bp_[3] = brow_[3];                               \
        _Pragma("unroll")                                                   \
        for (int i = 0; i < 8; i++) a_[i] = As[k][(ty) * 8 + i];            \
        _Pragma("unroll")                                                   \
        for (int i = 0; i < 8; i++) {                                       \
            u64 aa_ = pack2(a_[i], a_[i]);                                  \
            _Pragma("unroll")                                               \
            for (int j = 0; j < 4; j++) ffma2(cp[i][j], aa_, bp_[j]);       \
        }                                                                   \
    }

// ---------------- K1: Y[t] = x @ W_types[t]  (M=n, K=128, N=128) ----------------
__global__ void __launch_bounds__(256) y_gemm(const float* __restrict__ x,
                                             const float* __restrict__ Wt,
                                             int n) {
    int t = blockIdx.y;
    int m0 = blockIdx.x * 128;
    const float* B = Wt + (size_t)t * D * D;
    float* C = g_Y + (size_t)t * n * D;

    __shared__ float As[KTILE][128];
    __shared__ float Bs[KTILE][128];

    int tid = threadIdx.x;
    int tx = tid & 15, ty = tid >> 4;
    int lm = tid >> 1;          // A loader: row 0..127
    int lk = (tid & 1) * 8;     // A loader: k offset 0/8
    int bk = tid >> 4;          // B loader: k row 0..15
    int bn = (tid & 15) * 8;    // B loader: col

    u64 cp[8][4];
    #pragma unroll
    for (int i = 0; i < 8; i++)
        #pragma unroll
        for (int j = 0; j < 4; j++) cp[i][j] = 0ull;

    for (int kt = 0; kt < D; kt += KTILE) {
        int gm = m0 + lm;
        float4 a0 = make_float4(0.f, 0.f, 0.f, 0.f), a1 = a0;
        if (gm < n) {
            const float* ap = x + (size_t)gm * D + kt + lk;
            a0 = *reinterpret_cast<const float4*>(ap);
            a1 = *reinterpret_cast<const float4*>(ap + 4);
        }
        As[lk + 0][lm] = a0.x; As[lk + 1][lm] = a0.y;
        As[lk + 2][lm] = a0.z; As[lk + 3][lm] = a0.w;
        As[lk + 4][lm] = a1.x; As[lk + 5][lm] = a1.y;
        As[lk + 6][lm] = a1.z; As[lk + 7][lm] = a1.w;
        const float* bp = B + (size_t)(kt + bk) * D + bn;
        *reinterpret_cast<float4*>(&Bs[bk][bn])     = *reinterpret_cast<const float4*>(bp);
        *reinterpret_cast<float4*>(&Bs[bk][bn + 4]) = *reinterpret_cast<const float4*>(bp + 4);
        __syncthreads();
        MMA_TILE_STEP(As, Bs, cp, tx, ty);
        __syncthreads();
    }
    #pragma unroll
    for (int i = 0; i < 8; i++) {
        int gm = m0 + ty * 8 + i;
        if (gm < n) {
            float2 f0 = unpack2(cp[i][0]), f1 = unpack2(cp[i][1]);
            float2 f2 = unpack2(cp[i][2]), f3 = unpack2(cp[i][3]);
            float* cpo = C + (size_t)gm * D + tx * 8;
            *reinterpret_cast<float4*>(cpo)     = make_float4(f0.x, f0.y, f1.x, f1.y);
            *reinterpret_cast<float4*>(cpo + 4) = make_float4(f2.x, f2.y, f3.x, f3.y);
        }
    }
}

// ---------------- K2: per-edge-tile H GEMM + scatter ----------------
__global__ void __launch_bounds__(256) edge_kernel(const float* __restrict__ ef,
                                                   const float* __restrict__ W1,
                                                   const float* __restrict__ b1,
                                                   const int* __restrict__ erow,
                                                   const int* __restrict__ ecol,
                                                   const int* __restrict__ etype,
                                                   int E, int n) {
    int m0 = blockIdx.x * 128;

    __shared__ float As[KTILE][128];
    __shared__ float Bs[KTILE][128];
    __shared__ float sb1[128];
    __shared__ int s_row[128], s_col[128], s_type[128];

    int tid = threadIdx.x;
    int tx = tid & 15, ty = tid >> 4;
    int lm = tid >> 1;
    int lk = (tid & 1) * 8;
    int bk = tid >> 4;
    int bn = (tid & 15) * 8;

    if (tid < 128) {
        sb1[tid] = b1[tid];
        int e = m0 + tid;
        if (e < E) {
            int r = erow[e];
            int t = etype[e];
            s_row[tid] = r;
            s_col[tid] = ecol[e];
            s_type[tid] = t;
            atomicAdd(&g_deg[(size_t)t * n + r], 1);
        }
    }

    u64 cp[8][4];
    #pragma unroll
    for (int i = 0; i < 8; i++)
        #pragma unroll
        for (int j = 0; j < 4; j++) cp[i][j] = 0ull;

    for (int kt = 0; kt < D; kt += KTILE) {
        int gm = m0 + lm;
        float4 a0 = make_float4(0.f, 0.f, 0.f, 0.f), a1 = a0;
        if (gm < E) {
            const float* ap = ef + (size_t)gm * D + kt + lk;
            a0 = *reinterpret_cast<const float4*>(ap);
            a1 = *reinterpret_cast<const float4*>(ap + 4);
        }
        As[lk + 0][lm] = a0.x; As[lk + 1][lm] = a0.y;
        As[lk + 2][lm] = a0.z; As[lk + 3][lm] = a0.w;
        As[lk + 4][lm] = a1.x; As[lk + 5][lm] = a1.y;
        As[lk + 6][lm] = a1.z; As[lk + 7][lm] = a1.w;
        const float* bp = W1 + (size_t)(kt + bk) * D + bn;
        *reinterpret_cast<float4*>(&Bs[bk][bn])     = *reinterpret_cast<const float4*>(bp);
        *reinterpret_cast<float4*>(&Bs[bk][bn + 4]) = *reinterpret_cast<const float4*>(bp + 4);
        __syncthreads();
        MMA_TILE_STEP(As, Bs, cp, tx, ty);
        __syncthreads();
    }

    // epilogue: relu + bias, scatter H and Y
    #pragma unroll
    for (int i = 0; i < 8; i++) {
        int le = ty * 8 + i;
        int e = m0 + le;
        if (e >= E) continue;
        int r = s_row[le];
        int cn = s_col[le];
        int t = s_type[le];
        float2 f0 = unpack2(cp[i][0]), f1 = unpack2(cp[i][1]);
        float2 f2 = unpack2(cp[i][2]), f3 = unpack2(cp[i][3]);
        float cvals[8] = {f0.x, f0.y, f1.x, f1.y, f2.x, f2.y, f3.x, f3.y};
        float h[8];
        #pragma unroll
        for (int j = 0; j < 8; j++) h[j] = fmaxf(cvals[j] + sb1[tx * 8 + j], 0.f);
        float* a2 = g_acc2 + (size_t)r * D + tx * 8;
        red_add_v4(a2,     make_float4(h[0], h[1], h[2], h[3]));
        red_add_v4(a2 + 4, make_float4(h[4], h[5], h[6], h[7]));
        const float4* yp = reinterpret_cast<const float4*>(
            g_Y + ((size_t)t * n + cn) * D + tx * 8);
        float4 y0 = yp[0], y1 = yp[1];
        float* a1 = g_acc1 + (size_t)r * D + tx * 8;
        red_add_v4(a1,     y0);
        red_add_v4(a1 + 4, y1);
    }
}

// ---------------- K3: out = LN(acc1 + acc2@W_e2 + x@W_self + biases) -> relu ----------------
__global__ void __launch_bounds__(256) final_kernel(const float* __restrict__ x,
                                                    const float* __restrict__ We2,
                                                    const float* __restrict__ Wself,
                                                    const float* __restrict__ bself,
                                                    const float* __restrict__ btypes,
                                                    const float* __restrict__ be2,
                                                    const float* __restrict__ lng,
                                                    const float* __restrict__ lnb,
                                                    float* __restrict__ out,
                                                    int n) {
    int m0 = blockIdx.x * 128;

    __shared__ float As[KTILE][128];
    __shared__ float Bs[KTILE][128];
    __shared__ float s_bself[128], s_be2[128], s_g[128], s_lb[128];
    __shared__ float s_bt[T_TYPES][128];

    int tid = threadIdx.x;
    int tx = tid & 15, ty = tid >> 4;
    int lm = tid >> 1;
    int lk = (tid & 1) * 8;
    int bk = tid >> 4;
    int bn = (tid & 15) * 8;

    if (tid < 128) {
        s_bself[tid] = bself[tid];
        s_be2[tid] = be2[tid];
        s_g[tid] = lng[tid];
        s_lb[tid] = lnb[tid];
        #pragma unroll
        for (int t = 0; t < T_TYPES; t++) s_bt[t][tid] = btypes[t * D + tid];
    }

    u64 cp[8][4];
    #pragma unroll
    for (int i = 0; i < 8; i++)
        #pragma unroll
        for (int j = 0; j < 4; j++) cp[i][j] = 0ull;

    // K = 256: [0,128) -> acc2 @ W_e2 ; [128,256) -> x @ W_self
    for (int kt = 0; kt < 2 * D; kt += KTILE) {
        int gm = m0 + lm;
        float4 a0 = make_float4(0.f, 0.f, 0.f, 0.f), a1 = a0;
        if (gm < n) {
            const float* asrc = (kt < D) ? (g_acc2 + (size_t)gm * D + kt + lk)
                                         : (x + (size_t)gm * D + (kt - D) + lk);
            a0 = *reinterpret_cast<const float4*>(asrc);
            a1 = *reinterpret_cast<const float4*>(asrc + 4);
        }
        As[lk + 0][lm] = a0.x; As[lk + 1][lm] = a0.y;
        As[lk + 2][lm] = a0.z; As[lk + 3][lm] = a0.w;
        As[lk + 4][lm] = a1.x; As[lk + 5][lm] = a1.y;
        As[lk + 6][lm] = a1.z; As[lk + 7][lm] = a1.w;
        const float* bsrc = (kt < D) ? (We2 + (size_t)(kt + bk) * D + bn)
                                     : (Wself + (size_t)(kt - D + bk) * D + bn);
        *reinterpret_cast<float4*>(&Bs[bk][bn])     = *reinterpret_cast<const float4*>(bsrc);
        *reinterpret_cast<float4*>(&Bs[bk][bn + 4]) = *reinterpret_cast<const float4*>(bsrc + 4);
        __syncthreads();
        MMA_TILE_STEP(As, Bs, cp, tx, ty);
        __syncthreads();
    }

    // epilogue: bias + LN + relu. Keep all lanes active for shuffles (clamp, guard stores).
    #pragma unroll
    for (int i = 0; i < 8; i++) {
        int gm = m0 + ty * 8 + i;
        int gmc = (gm < n) ? gm : (n - 1);
        int d0 = g_deg[0 * (size_t)n + gmc];
        int d1 = g_deg[1 * (size_t)n + gmc];
        int d2 = g_deg[2 * (size_t)n + gmc];
        int d3 = g_deg[3 * (size_t)n + gmc];
        float degs = (float)(d0 + d1 + d2 + d3);
        const float4* a1p = reinterpret_cast<const float4*>(g_acc1 + (size_t)gmc * D + tx * 8);
        float4 a10 = a1p[0], a11 = a1p[1];
        float av[8] = {a10.x, a10.y, a10.z, a10.w, a11.x, a11.y, a11.z, a11.w};
        float2 f0 = unpack2(cp[i][0]), f1 = unpack2(cp[i][1]);
        float2 f2 = unpack2(cp[i][2]), f3 = unpack2(cp[i][3]);
        float cvals[8] = {f0.x, f0.y, f1.x, f1.y, f2.x, f2.y, f3.x, f3.y};
        float v[8];
        #pragma unroll
        for (int j = 0; j < 8; j++) {
            int col = tx * 8 + j;
            v[j] = cvals[j] + av[j] + s_bself[col]
                 + (float)d0 * s_bt[0][col] + (float)d1 * s_bt[1][col]
                 + (float)d2 * s_bt[2][col] + (float)d3 * s_bt[3][col]
                 + degs * s_be2[col];
        }
        float s = 0.f, sq = 0.f;
        #pragma unroll
        for (int j = 0; j < 8; j++) { s += v[j]; sq += v[j] * v[j]; }
        #pragma unroll
        for (int off = 8; off >= 1; off >>= 1) {
            s  += __shfl_xor_sync(0xffffffffu, s,  off);
            sq += __shfl_xor_sync(0xffffffffu, sq, off);
        }
        float mu = s * (1.f / 128.f);
        float var = sq * (1.f / 128.f) - mu * mu;
        float inv = rsqrtf(fmaxf(var, 0.f) + EPS);
        if (gm < n) {
            float o[8];
            #pragma unroll
            for (int j = 0; j < 8; j++) {
                int col = tx * 8 + j;
                o[j] = fmaxf((v[j] - mu) * inv * s_g[col] + s_lb[col], 0.f);
            }
            float* op = out + (size_t)gm * D + tx * 8;
            *reinterpret_cast<float4*>(op)     = make_float4(o[0], o[1], o[2], o[3]);
            *reinterpret_cast<float4*>(op + 4) = make_float4(o[4], o[5], o[6], o[7]);
        }
    }
}

// ---------------- launch ----------------
extern "C" void kernel_launch(void* const* d_in, const int* in_sizes, int n_in,
                              void* d_out, int out_size) {
    const float* x    = (const float*)d_in[0];
    const int*   ei   = (const int*)d_in[1];
    const int*   etyp = (const int*)d_in[2];
    const float* ef   = (const float*)d_in[3];
    const float* Wt   = (const float*)d_in[4];
    const float* bt   = (const float*)d_in[5];
    const float* Ws   = (const float*)d_in[6];
    const float* bs   = (const float*)d_in[7];
    const float* W1   = (const float*)d_in[8];
    const float* b1   = (const float*)d_in[9];
    const float* W2   = (const float*)d_in[10];
    const float* b2   = (const float*)d_in[11];
    const float* lg   = (const float*)d_in[12];
    const float* lb   = (const float*)d_in[13];
    float* out = (float*)d_out;

    int E = in_sizes[2];
    int n = in_sizes[0] / D;
    const int* erow = ei;       // edge_index[0] = destination (segment ids)
    const int* ecol = ei + E;   // edge_index[1] = source (gather ids)

    zero_kernel<<<1024, 256>>>(n);
    dim3 gy((n + 127) / 128, T_TYPES);
    y_gemm<<<gy, 256>>>(x, Wt, n);
    edge_kernel<<<(E + 127) / 128, 256>>>(ef, W1, b1, erow, ecol, etyp, E, n);
    final_kernel<<<(n + 127) / 128, 256>>>(x, W2, Ws, bs, bt, b2, lg, lb, out, n);
}

// round 4
// speedup vs baseline: 1.3717x; 1.2928x over previous
#include <cuda_runtime.h>
#include <cuda_bf16.h>
#include <cstdint>

#define D 128
#define T_TYPES 4
#define MAX_N 50000
#define MAX_E 500000
#define EPS 1e-5f

// smem layout (dynamic): bf16 tiles with 136-element (272B) row stride
#define SPAD_B 272
#define OFF_AHI 0
#define OFF_ALO 34816
#define OFF_BHI 69632
#define OFF_BLO 104448
#define DSMEM_BYTES 139264
// final kernel C-stage aliases A region: f32, row stride 133 words
#define C_STRIDE 133

typedef unsigned long long u64;

// ---------------- scratch ----------------
__device__ float g_S[(size_t)T_TYPES * MAX_N * D];   // per-type summed source features
__device__ float g_acc2[(size_t)MAX_N * D];          // scattered H = relu(EF@W1+b1)
__device__ int   g_deg[T_TYPES * MAX_N];
// preconverted weights bf16 hi/lo, layout Bt[n][k] = W[k][n]
// mats: 0..3 = W_types, 4 = W_e1, 5 = W_e2, 6 = W_self
__device__ __nv_bfloat16 g_Whi[7][128 * 128];
__device__ __nv_bfloat16 g_Wlo[7][128 * 128];

// ---------------- helpers ----------------
__device__ __forceinline__ void red_add_v4(float* addr, float4 v) {
    asm volatile("red.global.add.v4.f32 [%0], {%1, %2, %3, %4};"
                 :: "l"(addr), "f"(v.x), "f"(v.y), "f"(v.z), "f"(v.w) : "memory");
}
__device__ __forceinline__ void red_add_v2(float* addr, float a, float b) {
    asm volatile("red.global.add.v2.f32 [%0], {%1, %2};"
                 :: "l"(addr), "f"(a), "f"(b) : "memory");
}
__device__ __forceinline__ uint32_t smem_u32(const void* p) {
    uint32_t a;
    asm("{ .reg .u64 t; cvta.to.shared.u64 t, %1; cvt.u32.u64 %0, t; }" : "=r"(a) : "l"(p));
    return a;
}
__device__ __forceinline__ void ldsm4(uint32_t* r, uint32_t addr) {
    asm volatile("ldmatrix.sync.aligned.m8n8.x4.shared.b16 {%0,%1,%2,%3}, [%4];"
                 : "=r"(r[0]), "=r"(r[1]), "=r"(r[2]), "=r"(r[3]) : "r"(addr));
}
__device__ __forceinline__ void mma16816(float* c, const uint32_t* a, const uint32_t* b) {
    asm volatile("mma.sync.aligned.m16n8k16.row.col.f32.bf16.bf16.f32 "
                 "{%0,%1,%2,%3}, {%4,%5,%6,%7}, {%8,%9}, {%0,%1,%2,%3};"
                 : "+f"(c[0]), "+f"(c[1]), "+f"(c[2]), "+f"(c[3])
                 : "r"(a[0]), "r"(a[1]), "r"(a[2]), "r"(a[3]), "r"(b[0]), "r"(b[1]));
}

// convert 128 rows of fp32 src into hi/lo bf16 smem tiles (rows >= limit -> 0)
__device__ __forceinline__ void convert_A(const float* __restrict__ src, int m0, int limit,
                                          char* dsm, int tid) {
    #pragma unroll 4
    for (int it = 0; it < 16; it++) {
        int fi = it * 256 + tid;
        int row = fi >> 5;
        int cg = (fi & 31) * 4;
        int gm = m0 + row;
        float4 v = make_float4(0.f, 0.f, 0.f, 0.f);
        if (gm < limit) v = *reinterpret_cast<const float4*>(src + (size_t)gm * D + cg);
        __nv_bfloat16 hx = __float2bfloat16(v.x), hy = __float2bfloat16(v.y);
        __nv_bfloat16 hz = __float2bfloat16(v.z), hw = __float2bfloat16(v.w);
        __nv_bfloat16 lx = __float2bfloat16(v.x - __bfloat162float(hx));
        __nv_bfloat16 ly = __float2bfloat16(v.y - __bfloat162float(hy));
        __nv_bfloat16 lz = __float2bfloat16(v.z - __bfloat162float(hz));
        __nv_bfloat16 lw = __float2bfloat16(v.w - __bfloat162float(hw));
        int bo = row * SPAD_B + cg * 2;
        uint2 hv, lv;
        hv.x = (uint32_t)__bfloat16_as_ushort(hx) | ((uint32_t)__bfloat16_as_ushort(hy) << 16);
        hv.y = (uint32_t)__bfloat16_as_ushort(hz) | ((uint32_t)__bfloat16_as_ushort(hw) << 16);
        lv.x = (uint32_t)__bfloat16_as_ushort(lx) | ((uint32_t)__bfloat16_as_ushort(ly) << 16);
        lv.y = (uint32_t)__bfloat16_as_ushort(lz) | ((uint32_t)__bfloat16_as_ushort(lw) << 16);
        *reinterpret_cast<uint2*>(dsm + OFF_AHI + bo) = hv;
        *reinterpret_cast<uint2*>(dsm + OFF_ALO + bo) = lv;
    }
}

// copy preconverted B tile ([n][k] bf16) into padded smem
__device__ __forceinline__ void copy_B(const __nv_bfloat16* ghi, const __nv_bfloat16* glo,
                                       char* dsm, int tid) {
    const uint4* sh = reinterpret_cast<const uint4*>(ghi);
    const uint4* sl = reinterpret_cast<const uint4*>(glo);
    #pragma unroll 4
    for (int it = 0; it < 8; it++) {
        int idx = it * 256 + tid;           // 2048 uint4 chunks
        int row = idx >> 4;
        int cb = (idx & 15) * 16;
        *reinterpret_cast<uint4*>(dsm + OFF_BHI + row * SPAD_B + cb) = sh[idx];
        *reinterpret_cast<uint4*>(dsm + OFF_BLO + row * SPAD_B + cb) = sl[idx];
    }
}

// warp GEMM: C[128x128] += A[128x128] * Bt^T, split-bf16 3-product, K=128
// warp tile m32 x n64; acc[2][8][4]
__device__ __forceinline__ void warp_gemm_k128(uint32_t sb, int lane, int m0w, int n0w,
                                               float acc[2][8][4]) {
    uint32_t aoff = (uint32_t)((m0w + (lane & 15)) * SPAD_B + (lane >> 4) * 16);
    uint32_t boff = (uint32_t)((n0w + (lane & 7) + ((lane >> 3) & 2) * 4) * SPAD_B
                               + ((lane >> 3) & 1) * 16);
    uint32_t Ahi = sb + OFF_AHI + aoff, Alo = sb + OFF_ALO + aoff;
    uint32_t Bhi = sb + OFF_BHI + boff, Blo = sb + OFF_BLO + boff;
    #pragma unroll
    for (int ks = 0; ks < 8; ks++) {
        uint32_t k2 = (uint32_t)ks * 32;
        uint32_t ah[2][4], al[2][4], bh[4][4], bl[4][4];
        #pragma unroll
        for (int mt = 0; mt < 2; mt++) {
            ldsm4(ah[mt], Ahi + mt * (16 * SPAD_B) + k2);
            ldsm4(al[mt], Alo + mt * (16 * SPAD_B) + k2);
        }
        #pragma unroll
        for (int q = 0; q < 4; q++) {
            ldsm4(bh[q], Bhi + q * (16 * SPAD_B) + k2);
            ldsm4(bl[q], Blo + q * (16 * SPAD_B) + k2);
        }
        #pragma unroll
        for (int mt = 0; mt < 2; mt++)
            #pragma unroll
            for (int q = 0; q < 4; q++) {
                mma16816(acc[mt][q * 2],     ah[mt], bh[q]);
                mma16816(acc[mt][q * 2],     ah[mt], bl[q]);
                mma16816(acc[mt][q * 2],     al[mt], bh[q]);
                mma16816(acc[mt][q * 2 + 1], ah[mt], bh[q] + 2);
                mma16816(acc[mt][q * 2 + 1], ah[mt], bl[q] + 2);
                mma16816(acc[mt][q * 2 + 1], al[mt], bh[q] + 2);
            }
    }
}

// ---------------- zero scratch ----------------
__global__ void zero_kernel(int n) {
    size_t idx = (size_t)blockIdx.x * blockDim.x + threadIdx.x;
    size_t stride = (size_t)gridDim.x * blockDim.x;
    float4 z = make_float4(0.f, 0.f, 0.f, 0.f);
    size_t nS = (size_t)T_TYPES * n * D / 4;
    for (size_t i = idx; i < nS; i += stride) reinterpret_cast<float4*>(g_S)[i] = z;
    size_t n2 = (size_t)n * D / 4;
    for (size_t i = idx; i < n2; i += stride) reinterpret_cast<float4*>(g_acc2)[i] = z;
    size_t nd = (size_t)T_TYPES * n;
    for (size_t i = idx; i < nd; i += stride) g_deg[i] = 0;
}

// ---------------- prep: weights -> bf16 hi/lo, Bt[n][k] = W[k][n] ----------------
__global__ void prep_kernel(const float* __restrict__ Wt, const float* __restrict__ W1,
                            const float* __restrict__ W2, const float* __restrict__ Ws) {
    int id = blockIdx.x * blockDim.x + threadIdx.x;
    if (id >= 7 * 128 * 128) return;
    int m = id >> 14;
    int e = id & 16383;
    int nrow = e >> 7;
    int k = e & 127;
    const float* W = (m < 4) ? (Wt + (size_t)m * 128 * 128)
                             : ((m == 4) ? W1 : ((m == 5) ? W2 : Ws));
    float v = W[k * 128 + nrow];
    __nv_bfloat16 hi = __float2bfloat16(v);
    __nv_bfloat16 lo = __float2bfloat16(v - __bfloat162float(hi));
    g_Whi[m][nrow * 128 + k] = hi;
    g_Wlo[m][nrow * 128 + k] = lo;
}

// ---------------- edge kernel: H=relu(EF@W1+b1) scatter; x gather->S_t scatter ----------------
__global__ void __launch_bounds__(256) edge_kernel(const float* __restrict__ x,
                                                   const float* __restrict__ ef,
                                                   const float* __restrict__ b1,
                                                   const int* __restrict__ erow,
                                                   const int* __restrict__ ecol,
                                                   const int* __restrict__ etype,
                                                   int E, int n) {
    extern __shared__ char dsm[];
    __shared__ float s_b1[128];
    __shared__ int s_r[128], s_c[128], s_t[128];

    int tid = threadIdx.x, lane = tid & 31, wid = tid >> 5;
    int m0 = blockIdx.x * 128;
    uint32_t sb = smem_u32(dsm);

    if (tid < 128) {
        s_b1[tid] = b1[tid];
        int e = m0 + tid;
        if (e < E) {
            int r = erow[e], t = etype[e];
            s_r[tid] = r; s_c[tid] = ecol[e]; s_t[tid] = t;
            atomicAdd(&g_deg[(size_t)t * n + r], 1);
        }
    }
    convert_A(ef, m0, E, dsm, tid);
    copy_B(g_Whi[4], g_Wlo[4], dsm, tid);
    __syncthreads();

    float acc[2][8][4];
    #pragma unroll
    for (int mt = 0; mt < 2; mt++)
        #pragma unroll
        for (int nt = 0; nt < 8; nt++)
            #pragma unroll
            for (int j = 0; j < 4; j++) acc[mt][nt][j] = 0.f;

    int m0w = (wid >> 1) * 32, n0w = (wid & 1) * 64;
    warp_gemm_k128(sb, lane, m0w, n0w, acc);

    // H epilogue: relu + bias -> red into g_acc2[row]
    #pragma unroll
    for (int mt = 0; mt < 2; mt++) {
        int er0 = m0w + mt * 16 + (lane >> 2);
        int er1 = er0 + 8;
        bool v0 = (m0 + er0) < E, v1 = (m0 + er1) < E;
        int r0 = v0 ? s_r[er0] : 0, r1 = v1 ? s_r[er1] : 0;
        #pragma unroll
        for (int nt = 0; nt < 8; nt++) {
            int cj = n0w + nt * 8 + (lane & 3) * 2;
            float bb0 = s_b1[cj], bb1 = s_b1[cj + 1];
            if (v0) {
                float h0 = fmaxf(acc[mt][nt][0] + bb0, 0.f);
                float h1 = fmaxf(acc[mt][nt][1] + bb1, 0.f);
                red_add_v2(g_acc2 + (size_t)r0 * D + cj, h0, h1);
            }
            if (v1) {
                float h2 = fmaxf(acc[mt][nt][2] + bb0, 0.f);
                float h3 = fmaxf(acc[mt][nt][3] + bb1, 0.f);
                red_add_v2(g_acc2 + (size_t)r1 * D + cj, h2, h3);
            }
        }
    }

    // x gather -> S_t scatter (2 threads per edge)
    {
        int el = tid >> 1;
        int half = (tid & 1) * 64;
        int e = m0 + el;
        if (e < E) {
            int r = s_r[el], cn = s_c[el], t = s_t[el];
            const float4* xs = reinterpret_cast<const float4*>(x + (size_t)cn * D + half);
            float* dst = g_S + ((size_t)t * n + r) * D + half;
            #pragma unroll
            for (int j = 0; j < 16; j++) red_add_v4(dst + 4 * j, xs[j]);
        }
    }
}

// ---------------- final: out = relu(LN(sum_t S_t@W_t + acc2@W2 + x@Wself + biases)) ------------
__global__ void __launch_bounds__(256) final_kernel(const float* __restrict__ x,
                                                    const float* __restrict__ bself,
                                                    const float* __restrict__ btypes,
                                                    const float* __restrict__ be2,
                                                    const float* __restrict__ lng,
                                                    const float* __restrict__ lnb,
                                                    float* __restrict__ out,
                                                    int n) {
    extern __shared__ char dsm[];
    __shared__ float s_bself[128], s_be2[128], s_g[128], s_lb[128];
    __shared__ float s_bt[T_TYPES][128];

    int tid = threadIdx.x, lane = tid & 31, wid = tid >> 5;
    int m0 = blockIdx.x * 128;
    uint32_t sb = smem_u32(dsm);

    if (tid < 128) {
        s_bself[tid] = bself[tid];
        s_be2[tid] = be2[tid];
        s_g[tid] = lng[tid];
        s_lb[tid] = lnb[tid];
        #pragma unroll
        for (int t = 0; t < T_TYPES; t++) s_bt[t][tid] = btypes[t * D + tid];
    }

    float acc[2][8][4];
    #pragma unroll
    for (int mt = 0; mt < 2; mt++)
        #pragma unroll
        for (int nt = 0; nt < 8; nt++)
            #pragma unroll
            for (int j = 0; j < 4; j++) acc[mt][nt][j] = 0.f;

    int m0w = (wid >> 1) * 32, n0w = (wid & 1) * 64;

    #pragma unroll 1
    for (int ph = 0; ph < 6; ph++) {
        const float* srcA;
        int mat;
        if (ph < 4)      { srcA = g_S + (size_t)ph * n * D; mat = ph; }
        else if (ph == 4){ srcA = g_acc2;                   mat = 5;  }
        else             { srcA = x;                        mat = 6;  }
        __syncthreads();
        convert_A(srcA, m0, n, dsm, tid);
        copy_B(g_Whi[mat], g_Wlo[mat], dsm, tid);
        __syncthreads();
        warp_gemm_k128(sb, lane, m0w, n0w, acc);
    }
    __syncthreads();   // all smem reads done; safe to alias C over A region

    // stage C into smem f32 [128][C_STRIDE]
    float* Cs = reinterpret_cast<float*>(dsm);
    #pragma unroll
    for (int mt = 0; mt < 2; mt++) {
        int er0 = m0w + mt * 16 + (lane >> 2);
        #pragma unroll
        for (int nt = 0; nt < 8; nt++) {
            int cj = n0w + nt * 8 + (lane & 3) * 2;
            Cs[er0 * C_STRIDE + cj]       = acc[mt][nt][0];
            Cs[er0 * C_STRIDE + cj + 1]   = acc[mt][nt][1];
            Cs[(er0 + 8) * C_STRIDE + cj]     = acc[mt][nt][2];
            Cs[(er0 + 8) * C_STRIDE + cj + 1] = acc[mt][nt][3];
        }
    }
    __syncthreads();

    // per-row LN (threads 0..127)
    if (tid < 128) {
        int gm = m0 + tid;
        if (gm < n) {
            int d0 = g_deg[0 * (size_t)n + gm];
            int d1 = g_deg[1 * (size_t)n + gm];
            int d2 = g_deg[2 * (size_t)n + gm];
            int d3 = g_deg[3 * (size_t)n + gm];
            float f0 = (float)d0, f1 = (float)d1, f2 = (float)d2, f3 = (float)d3;
            float degs = f0 + f1 + f2 + f3;
            float* row = Cs + tid * C_STRIDE;
            float s = 0.f, sq = 0.f;
            #pragma unroll 8
            for (int j = 0; j < 128; j++) {
                float val = row[j] + s_bself[j]
                          + f0 * s_bt[0][j] + f1 * s_bt[1][j]
                          + f2 * s_bt[2][j] + f3 * s_bt[3][j]
                          + degs * s_be2[j];
                row[j] = val;
                s += val; sq += val * val;
            }
            float mu = s * (1.f / 128.f);
            float var = sq * (1.f / 128.f) - mu * mu;
            float inv = rsqrtf(fmaxf(var, 0.f) + EPS);
            float* op = out + (size_t)gm * D;
            #pragma unroll 8
            for (int j = 0; j < 32; j++) {
                float4 o;
                o.x = fmaxf((row[4*j+0] - mu) * inv * s_g[4*j+0] + s_lb[4*j+0], 0.f);
                o.y = fmaxf((row[4*j+1] - mu) * inv * s_g[4*j+1] + s_lb[4*j+1], 0.f);
                o.z = fmaxf((row[4*j+2] - mu) * inv * s_g[4*j+2] + s_lb[4*j+2], 0.f);
                o.w = fmaxf((row[4*j+3] - mu) * inv * s_g[4*j+3] + s_lb[4*j+3], 0.f);
                *reinterpret_cast<float4*>(op + 4 * j) = o;
            }
        }
    }
}

// ---------------- launch ----------------
extern "C" void kernel_launch(void* const* d_in, const int* in_sizes, int n_in,
                              void* d_out, int out_size) {
    const float* x    = (const float*)d_in[0];
    const int*   ei   = (const int*)d_in[1];
    const int*   etyp = (const int*)d_in[2];
    const float* ef   = (const float*)d_in[3];
    const float* Wt   = (const float*)d_in[4];
    const float* bt   = (const float*)d_in[5];
    const float* Ws   = (const float*)d_in[6];
    const float* bs   = (const float*)d_in[7];
    const float* W1   = (const float*)d_in[8];
    const float* b1   = (const float*)d_in[9];
    const float* W2   = (const float*)d_in[10];
    const float* b2   = (const float*)d_in[11];
    const float* lg   = (const float*)d_in[12];
    const float* lb   = (const float*)d_in[13];
    float* out = (float*)d_out;

    int E = in_sizes[2];
    int n = in_sizes[0] / D;
    const int* erow = ei;       // destinations (segment ids)
    const int* ecol = ei + E;   // sources (gather ids)

    cudaFuncSetAttribute(edge_kernel, cudaFuncAttributeMaxDynamicSharedMemorySize, DSMEM_BYTES);
    cudaFuncSetAttribute(final_kernel, cudaFuncAttributeMaxDynamicSharedMemorySize, DSMEM_BYTES);

    zero_kernel<<<1024, 256>>>(n);
    prep_kernel<<<(7 * 128 * 128 + 255) / 256, 256>>>(Wt, W1, W2, Ws);
    edge_kernel<<<(E + 127) / 128, 256, DSMEM_BYTES>>>(x, ef, b1, erow, ecol, etyp, E, n);
    final_kernel<<<(n + 127) / 128, 256, DSMEM_BYTES>>>(x, bs, bt, b2, lg, lb, out, n);
}